// round 13
// baseline (speedup 1.0000x reference)
#include <cuda_runtime.h>
#include <cuda_fp16.h>
#include <cstdint>

// ============================================================================
// B=8, N=256, M=256, T=512, H=16, D=64, DIM=1024.
// Window: j in [i, i+256]; delta = j-i; Ppad[bh][i][delta+64] holds
// 0.125*(q.RW + c + dt) for valid delta, -1e30 otherwise (q pre-scaled).
// Round 13: dense GEMM tile 128x256 (warp 64x64), 1 CTA/SM — amortize the
// smem crossbar (was ~150B/cyc vs 128 cap) over 2x MMA work per kt.
// A = fp16 hi+lo (exact), B = single fp16 -> 2 MMAs/tile.
// ============================================================================

__device__ __half g_RWh[1024u * 1024u];
__device__ __half g_RWl[1024u * 1024u];
__device__ __half g_qh[8u*16u*256u*64u], g_ql[8u*16u*256u*64u];
__device__ __half g_kh[8u*16u*512u*64u], g_kl[8u*16u*512u*64u];
__device__ __half g_vh[8u*16u*512u*64u], g_vl[8u*16u*512u*64u];
__device__ float g_Pp[8u * 16u * 256u * 384u];         // padded biased scores
__device__ float g_c [8u * 16u * 512u];
__device__ float g_dt[16u * 257u];

__device__ __half g_Ah [4096u * 1024u], g_Al [4096u * 1024u];  // cat(h,x) split
__device__ __half g_ARh[1024u * 1024u], g_ARl[1024u * 1024u];  // R split
__device__ __half g_B  [3072u * 1024u];                         // Wqkv^T single
__device__ __half g_BK [1024u * 1024u];                         // Wkr^T single
__device__ __half g_BO [1024u * 1024u];                         // Wout^T single
__device__ __half g_Oh [2048u * 1024u], g_Ol [2048u * 1024u];  // attn out split

// ============================================================================
// PTX helpers
// ============================================================================
__device__ __forceinline__ uint32_t smem_u32(const void* p) {
    uint32_t a;
    asm("{ .reg .u64 t; cvta.to.shared.u64 t, %1; cvt.u32.u64 %0, t; }"
        : "=r"(a) : "l"(p));
    return a;
}
__device__ __forceinline__ void cp16(uint32_t saddr, const void* g) {
    asm volatile("cp.async.cg.shared.global [%0], [%1], 16;"
                 :: "r"(saddr), "l"(g) : "memory");
}
#define CP_COMMIT() asm volatile("cp.async.commit_group;" ::: "memory")
#define CP_WAIT1()  asm volatile("cp.async.wait_group 1;" ::: "memory")
#define CP_WAIT0()  asm volatile("cp.async.wait_group 0;" ::: "memory")

__device__ __forceinline__ void ldsm4(uint32_t* r, uint32_t addr) {
    asm volatile("ldmatrix.sync.aligned.m8n8.x4.shared.b16 {%0,%1,%2,%3}, [%4];"
                 : "=r"(r[0]), "=r"(r[1]), "=r"(r[2]), "=r"(r[3]) : "r"(addr));
}
__device__ __forceinline__ void ldsm4t(uint32_t* r, uint32_t addr) {
    asm volatile("ldmatrix.sync.aligned.m8n8.x4.trans.shared.b16 {%0,%1,%2,%3}, [%4];"
                 : "=r"(r[0]), "=r"(r[1]), "=r"(r[2]), "=r"(r[3]) : "r"(addr));
}
// fp16 inputs, fp32 accumulate
__device__ __forceinline__ void mma16816h(float* c, const uint32_t* a,
                                          const uint32_t* b) {
    asm volatile(
        "mma.sync.aligned.m16n8k16.row.col.f32.f16.f16.f32 "
        "{%0,%1,%2,%3}, {%4,%5,%6,%7}, {%8,%9}, {%0,%1,%2,%3};"
        : "+f"(c[0]), "+f"(c[1]), "+f"(c[2]), "+f"(c[3])
        : "r"(a[0]), "r"(a[1]), "r"(a[2]), "r"(a[3]), "r"(b[0]), "r"(b[1]));
}

__device__ __forceinline__ unsigned short hbits(__half x) {
    return *reinterpret_cast<unsigned short*>(&x);
}
__device__ __forceinline__ void pack2h(float a, float b, uint32_t& H, uint32_t& L) {
    __half ah = __float2half_rn(a), bh = __float2half_rn(b);
    __half al = __float2half_rn(a - __half2float(ah));
    __half bl = __float2half_rn(b - __half2float(bh));
    H = (uint32_t)hbits(ah) | ((uint32_t)hbits(bh) << 16);
    L = (uint32_t)hbits(al) | ((uint32_t)hbits(bl) << 16);
}

// ============================================================================
// Dense mma GEMM: CTA 128x256, BK=32, 2-stage cp.async, 80B smem rows,
// warp tile 64x64 (2x4 warps). A = fp16 hi/lo split, B = single fp16.
// smem stage: Ah[128x80] Al[128x80] B[256x80] = 40KB; double = 80KB; 1 CTA/SM.
// mode 0: fp32 C. mode 1: qkv scatter (q pre-scaled). mode 2: RW fp16 split.
// gridDim.z==2 merges the RW GEMM (z=1, 4x8 jobs) into the qkv launch (z=0).
// ============================================================================
#define MG_A0 0
#define MG_A1 10240
#define MG_B0 20480
#define MG_STG 40960
#define MG_SMEM (2 * MG_STG)             // 81920

__device__ __forceinline__ void qkv_scatter(int gr, int gc, float v0, float v1) {
    int b = gr >> 9, tt = gr & 511;
    int sec = gc >> 10, c2 = gc & 1023, hh = c2 >> 6, d = c2 & 63;
    if (sec == 0) {
        if (tt >= 256) {
            uint32_t H, L; pack2h(v0 * 0.125f, v1 * 0.125f, H, L);
            size_t o = (((size_t)b * 16 + hh) * 256 + (tt - 256)) * 64 + d;
            *(uint32_t*)&g_qh[o] = H; *(uint32_t*)&g_ql[o] = L;
        }
    } else {
        uint32_t H, L; pack2h(v0, v1, H, L);
        size_t o = (((size_t)b * 16 + hh) * 512 + tt) * 64 + d;
        if (sec == 1) { *(uint32_t*)&g_kh[o] = H; *(uint32_t*)&g_kl[o] = L; }
        else          { *(uint32_t*)&g_vh[o] = H; *(uint32_t*)&g_vl[o] = L; }
    }
}

__global__ __launch_bounds__(256, 1) void mma_gemm(
    const __half* __restrict__ Ah, const __half* __restrict__ Al,
    const __half* __restrict__ Bs,
    float* __restrict__ C, int ldc, int mode)
{
    int bx = blockIdx.x, by = blockIdx.y;
    if (blockIdx.z == 1) {
        if (bx >= 4 || by >= 8) return;      // merged RW GEMM: R @ Wkr (1024x1024)
        Ah = g_ARh; Al = g_ARl; Bs = g_BK;
        mode = 2;
    } else {
        if (mode == 1 && bx < 4 && (by & 3) < 2) return;  // q for memory rows
    }

    extern __shared__ char smc[];
    uint32_t sb = smem_u32(smc);
    int tid = threadIdx.x, lane = tid & 31, wid = tid >> 5;
    int wm = wid >> 2, wn = wid & 3;                      // 2 x 4, warp 64x64

    const __half* gA[2] = { Ah, Al };

    // one stage = 2048 16B-chunks: Ah 512, Al 512, B 1024; 8 per thread.
    auto load_stage = [&](int s, int kt) {
#pragma unroll
        for (int l = 0; l < 8; l++) {
            int idx = tid + l * 256;
            uint32_t dst;
            const __half* gp;
            if (idx < 1024) {
                int arr = idx >> 9, e = idx & 511;
                int row = e >> 2, c = e & 3;
                gp = gA[arr] + (size_t)(by * 128 + row) * 1024 + kt * 32 + c * 8;
                dst = sb + s * MG_STG + arr * 10240 + (uint32_t)(row * 80 + c * 16);
            } else {
                int e = idx - 1024;
                int row = e >> 2, c = e & 3;
                gp = Bs + (size_t)(bx * 256 + row) * 1024 + kt * 32 + c * 8;
                dst = sb + s * MG_STG + MG_B0 + (uint32_t)(row * 80 + c * 16);
            }
            cp16(dst, gp);
        }
        CP_COMMIT();
    };

    float acc[32][4];
#pragma unroll
    for (int i = 0; i < 32; i++)
#pragma unroll
        for (int j = 0; j < 4; j++) acc[i][j] = 0.f;

    load_stage(0, 0);

    for (int kt = 0; kt < 32; kt++) {
        if (kt + 1 < 32) { load_stage((kt + 1) & 1, kt + 1); CP_WAIT1(); }
        else             { CP_WAIT0(); }
        __syncthreads();

        uint32_t stg = sb + (kt & 1) * MG_STG;
#pragma unroll
        for (int kk = 0; kk < 2; kk++) {
            uint32_t afh[4][4], afl[4][4];
            {
                int row = wm * 64 + (lane & 15);
                int c   = kk * 2 + (lane >> 4);
                uint32_t off = (uint32_t)(row * 80 + c * 16);
#pragma unroll
                for (int t = 0; t < 4; t++) {
                    ldsm4(afh[t], stg + MG_A0 + off + t * (16 * 80));
                    ldsm4(afl[t], stg + MG_A1 + off + t * (16 * 80));
                }
            }
            uint32_t bf[16];                 // 8 n8-tiles x 2 regs
            {
                int n = wn * 64 + ((lane >> 4) * 8 + (lane & 7));
                int c = kk * 2 + ((lane >> 3) & 1);
                uint32_t off = (uint32_t)(n * 80 + c * 16);
#pragma unroll
                for (int g2 = 0; g2 < 4; g2++)
                    ldsm4(&bf[g2 * 4], stg + MG_B0 + off + g2 * (16 * 80));
            }
#pragma unroll
            for (int t = 0; t < 4; t++)
#pragma unroll
                for (int n = 0; n < 8; n++) {
                    float* cc = acc[t * 8 + n];
                    mma16816h(cc, afh[t], &bf[n * 2]);
                    mma16816h(cc, afl[t], &bf[n * 2]);
                }
        }
        __syncthreads();
    }

#pragma unroll
    for (int t = 0; t < 4; t++)
#pragma unroll
        for (int n = 0; n < 8; n++) {
            int gr = by * 128 + wm * 64 + t * 16 + (lane >> 2);
            int gc = bx * 256 + wn * 64 + n * 8 + (lane & 3) * 2;
            float* cc = acc[t * 8 + n];
            if (mode == 0) {
                *(float2*)&C[(size_t)gr * ldc + gc]       = make_float2(cc[0], cc[1]);
                *(float2*)&C[(size_t)(gr + 8) * ldc + gc] = make_float2(cc[2], cc[3]);
            } else if (mode == 2) {
                uint32_t H, L;
                pack2h(cc[0], cc[1], H, L);
                *(uint32_t*)&g_RWh[(size_t)gr * 1024 + gc] = H;
                *(uint32_t*)&g_RWl[(size_t)gr * 1024 + gc] = L;
                pack2h(cc[2], cc[3], H, L);
                *(uint32_t*)&g_RWh[(size_t)(gr + 8) * 1024 + gc] = H;
                *(uint32_t*)&g_RWl[(size_t)(gr + 8) * 1024 + gc] = L;
            } else {
                qkv_scatter(gr, gc, cc[0], cc[1]);
                qkv_scatter(gr + 8, gc, cc[2], cc[3]);
            }
        }
}

// ============================================================================
// Conversions
// ============================================================================
__device__ __forceinline__ void split4h(float4 v, uint2& H, uint2& L) {
    uint32_t h0, l0, h1, l1;
    pack2h(v.x, v.y, h0, l0);
    pack2h(v.z, v.w, h1, l1);
    H.x = h0; H.y = h1; L.x = l0; L.y = l1;
}

// weight transposes -> single fp16: z=0 Wqkv, z=1 Wkr, z=2 Wout
__global__ __launch_bounds__(256) void conv_all_T(
    const float* __restrict__ Wqkv, const float* __restrict__ Wkr,
    const float* __restrict__ Wout)
{
    int z = blockIdx.z;
    const float* W; __half* Th; int N;
    if (z == 0)      { W = Wqkv; Th = g_B;  N = 3072; }
    else if (z == 1) { if (blockIdx.x >= 32) return; W = Wkr;  Th = g_BK; N = 1024; }
    else             { if (blockIdx.x >= 32) return; W = Wout; Th = g_BO; N = 1024; }

    __shared__ float ts[32][33];
    int n0 = blockIdx.x * 32, k0 = blockIdx.y * 32;
    int tx = threadIdx.x & 31, ty = threadIdx.x >> 5;
#pragma unroll
    for (int r = 0; r < 32; r += 8)
        ts[ty + r][tx] = W[(size_t)(k0 + ty + r) * N + n0 + tx];
    __syncthreads();
#pragma unroll
    for (int r = 0; r < 32; r += 8) {
        float v = ts[tx][ty + r];
        Th[(size_t)(n0 + ty + r) * 1024 + k0 + tx] = __float2half_rn(v);
    }
}

// cat(h,x) -> g_Ah/g_Al split (blocks 0..4095); R -> g_ARh/g_ARl (4096..5119)
__global__ __launch_bounds__(256) void conv_A(
    const float* __restrict__ x, const float* __restrict__ h,
    const float* __restrict__ R)
{
    int blk = blockIdx.x;
    if (blk < 4096) {
        int i = blk * 256 + threadIdx.x;
        int row = i >> 8, c4 = i & 255;
        int b = row >> 9, t = row & 511;
        const float4* src = (const float4*)((t < 256)
            ? (h + ((size_t)b * 256 + t) * 1024)
            : (x + ((size_t)b * 256 + (t - 256)) * 1024));
        uint2 H, L;
        split4h(src[c4], H, L);
        ((uint2*)g_Ah)[i] = H; ((uint2*)g_Al)[i] = L;
    } else {
        int i = (blk - 4096) * 256 + threadIdx.x;
        uint2 H, L;
        split4h(((const float4*)R)[i], H, L);
        ((uint2*)g_ARh)[i] = H; ((uint2*)g_ARl)[i] = L;
    }
}

// cterm (blocks 0..8191) + dterm (8192..8705); reconstruct hi+lo in fp32
__global__ __launch_bounds__(256) void cdterm(const float* __restrict__ u,
                                              const float* __restrict__ v)
{
    int blk = blockIdx.x;
    int lane = threadIdx.x & 31;
    if (blk < 8192) {
        int row = blk * 8 + (threadIdx.x >> 5);
        size_t o = (size_t)row * 64 + lane;
        float k0 = __half2float(g_kh[o]) + __half2float(g_kl[o]);
        float k1 = __half2float(g_kh[o + 32]) + __half2float(g_kl[o + 32]);
        float s = u[lane] * k0 + u[lane + 32] * k1;
#pragma unroll
        for (int of = 16; of; of >>= 1) s += __shfl_xor_sync(0xffffffffu, s, of);
        if (lane == 0) g_c[row] = s;
    } else {
        int row = (blk - 8192) * 8 + (threadIdx.x >> 5);
        if (row >= 16 * 257) return;
        int hh = row / 257, t = row % 257;
        size_t base = (size_t)((t + 768) & 1023) * 1024 + hh * 64;
        float r0 = __half2float(g_RWh[base + lane]) + __half2float(g_RWl[base + lane]);
        float r1 = __half2float(g_RWh[base + lane + 32])
                 + __half2float(g_RWl[base + lane + 32]);
        float s = v[lane] * r0 + v[lane + 32] * r1;
#pragma unroll
        for (int of = 16; of; of >>= 1) s += __shfl_xor_sync(0xffffffffu, s, of);
        if (lane == 0) g_dt[row] = s;
    }
}

// ============================================================================
// P GEMM -> Ppad[bh][i][idx], idx = delta + 64 in [0,384). fp16 3-MMA.
// ============================================================================
#define PG_LDB 144
__global__ __launch_bounds__(256) void p_gemm2()
{
    __shared__ char sm2[4 * 64 * PG_LDB];
    int tt = blockIdx.x, it = blockIdx.y, bh = blockIdx.z;
    int hh = bh & 15;
    int i0 = it * 64;
    int tid = threadIdx.x, lane = tid & 31, wid = tid >> 5;

    if (tt == 0) {
        for (int e = tid; e < 4096; e += 256) {
            int row = e >> 6, idx = e & 63;
            g_Pp[((size_t)bh * 256 + i0 + row) * 384 + idx] = -1e30f;
        }
        return;
    }

    uint32_t sb = smem_u32(sm2);
    uint32_t sQh = sb, sQl = sb + 9216, sBh = sb + 18432, sBl = sb + 27648;
    int wm = wid >> 1, wn = wid & 1;

#pragma unroll
    for (int l = 0; l < 2; l++) {
        int e = tid + l * 256;
        int row = e >> 3, c = e & 7;
        size_t qo = ((size_t)bh * 256 + i0 + row) * 64 + c * 8;
        *(uint4*)(sm2 + row * PG_LDB + c * 16) = *(const uint4*)&g_qh[qo];
        *(uint4*)(sm2 + 9216 + row * PG_LDB + c * 16) = *(const uint4*)&g_ql[qo];
        int t = (tt - 1) * 64 + row;
        int rr = (t + 768) & 1023;
        size_t bo = (size_t)rr * 1024 + hh * 64 + c * 8;
        *(uint4*)(sm2 + 18432 + row * PG_LDB + c * 16) = *(const uint4*)&g_RWh[bo];
        *(uint4*)(sm2 + 27648 + row * PG_LDB + c * 16) = *(const uint4*)&g_RWl[bo];
    }
    __syncthreads();

    float acc[4][4];
#pragma unroll
    for (int n = 0; n < 4; n++)
#pragma unroll
        for (int j = 0; j < 4; j++) acc[n][j] = 0.f;

#pragma unroll
    for (int kk = 0; kk < 4; kk++) {
        uint32_t afh[4], afl[4];
        {
            int row = wm * 16 + (lane & 15);
            uint32_t off = (uint32_t)(row * PG_LDB + kk * 32 + (lane >> 4) * 16);
            ldsm4(afh, sQh + off);
            ldsm4(afl, sQl + off);
        }
        uint32_t bfh[8], bfl[8];
        {
            int n = wn * 32 + ((lane >> 4) * 8 + (lane & 7));
            uint32_t off = (uint32_t)(n * PG_LDB + kk * 32 + ((lane >> 3) & 1) * 16);
            ldsm4(&bfh[0], sBh + off);
            ldsm4(&bfh[4], sBh + off + 16 * PG_LDB);
            ldsm4(&bfl[0], sBl + off);
            ldsm4(&bfl[4], sBl + off + 16 * PG_LDB);
        }
#pragma unroll
        for (int n = 0; n < 4; n++) {
            mma16816h(acc[n], afh, &bfh[n * 2]);
            mma16816h(acc[n], afh, &bfl[n * 2]);
            mma16816h(acc[n], afl, &bfh[n * 2]);
        }
    }

#pragma unroll
    for (int n = 0; n < 4; n++) {
        int tl = wn * 32 + n * 8 + (lane & 3) * 2;
#pragma unroll
        for (int half = 0; half < 2; half++) {
            int ii = i0 + wm * 16 + (lane >> 2) + half * 8;
#pragma unroll
            for (int e = 0; e < 2; e++) {
                int t = (tt - 1) * 64 + tl + e;
                float a = acc[n][half * 2 + e];
                float val = -1e30f;
                if (t < 257)
                    val = a + 0.125f * (g_c[(size_t)bh * 512 + ii + t]
                                        + g_dt[hh * 257 + t]);
                g_Pp[((size_t)bh * 256 + ii) * 384 + t + 64] = val;
            }
        }
    }
}

// ============================================================================
// Fused attention (register softmax), fp16 3-MMA
// ============================================================================
#define AT_LDB 144
__global__ __launch_bounds__(256) void attn_mma2()
{
    __shared__ char sma[36864 + 1024];
    uint32_t sb = smem_u32(sma);
    uint32_t sQh = sb, sQl = sb + 9216;
    uint32_t sKh = sb + 18432, sKl = sb + 27648;
    float* sRed = (float*)(sma + 36864);
    float* sO   = (float*)sma;

    int it = blockIdx.x, bh = blockIdx.y;
    int hh = bh & 15, bb = bh >> 4;
    int i0 = it * 64;
    int tid = threadIdx.x, lane = tid & 31, wid = tid >> 5;
    int wm = wid >> 1, wn = wid & 1;

#pragma unroll
    for (int l = 0; l < 2; l++) {
        int e = tid + l * 256, row = e >> 3, c = e & 7;
        size_t qo = ((size_t)bh * 256 + i0 + row) * 64 + c * 8;
        *(uint4*)(sma + row * AT_LDB + c * 16) = *(const uint4*)&g_qh[qo];
        *(uint4*)(sma + 9216 + row * AT_LDB + c * 16) = *(const uint4*)&g_ql[qo];
    }

    float sc[5][4][4];
#pragma unroll
    for (int jt = 0; jt < 5; jt++)
#pragma unroll
        for (int n = 0; n < 4; n++)
#pragma unroll
            for (int j = 0; j < 4; j++) sc[jt][n][j] = 0.f;

#pragma unroll
    for (int jt = 0; jt < 5; jt++) {
#pragma unroll
        for (int l = 0; l < 2; l++) {
            int e = tid + l * 256, row = e >> 3, c = e & 7;
            size_t ko = ((size_t)bh * 512 + i0 + jt * 64 + row) * 64 + c * 8;
            *(uint4*)(sma + 18432 + row * AT_LDB + c * 16) = *(const uint4*)&g_kh[ko];
            *(uint4*)(sma + 27648 + row * AT_LDB + c * 16) = *(const uint4*)&g_kl[ko];
        }
        __syncthreads();
#pragma unroll
        for (int kk = 0; kk < 4; kk++) {
            uint32_t afh[4], afl[4];
            {
                int row = wm * 16 + (lane & 15);
                uint32_t off = (uint32_t)(row * AT_LDB + kk * 32 + (lane >> 4) * 16);
                ldsm4(afh, sQh + off);
                ldsm4(afl, sQl + off);
            }
            uint32_t bfh[8], bfl[8];
            {
                int n = wn * 32 + ((lane >> 4) * 8 + (lane & 7));
                uint32_t off = (uint32_t)(n * AT_LDB + kk * 32 + ((lane >> 3) & 1) * 16);
                ldsm4(&bfh[0], sKh + off);
                ldsm4(&bfh[4], sKh + off + 16 * AT_LDB);
                ldsm4(&bfl[0], sKl + off);
                ldsm4(&bfl[4], sKl + off + 16 * AT_LDB);
            }
#pragma unroll
            for (int n = 0; n < 4; n++) {
                mma16816h(sc[jt][n], afh, &bfh[n * 2]);
                mma16816h(sc[jt][n], afh, &bfl[n * 2]);
                mma16816h(sc[jt][n], afl, &bfh[n * 2]);
            }
        }
        __syncthreads();
    }

    int r1 = wm * 16 + (lane >> 2), r2 = r1 + 8;
    const float* P1 = &g_Pp[((size_t)bh * 256 + i0 + r1) * 384 + 64 - r1];
    const float* P2 = &g_Pp[((size_t)bh * 256 + i0 + r2) * 384 + 64 - r2];
    float m1 = -1e30f, m2 = -1e30f;
#pragma unroll
    for (int jt = 0; jt < 5; jt++)
#pragma unroll
        for (int n = 0; n < 4; n++) {
            int col = jt * 64 + wn * 32 + n * 8 + (lane & 3) * 2;
            sc[jt][n][0] += P1[col];     sc[jt][n][1] += P1[col + 1];
            sc[jt][n][2] += P2[col];     sc[jt][n][3] += P2[col + 1];
            m1 = fmaxf(m1, fmaxf(sc[jt][n][0], sc[jt][n][1]));
            m2 = fmaxf(m2, fmaxf(sc[jt][n][2], sc[jt][n][3]));
        }
    m1 = fmaxf(m1, __shfl_xor_sync(0xffffffffu, m1, 1));
    m1 = fmaxf(m1, __shfl_xor_sync(0xffffffffu, m1, 2));
    m2 = fmaxf(m2, __shfl_xor_sync(0xffffffffu, m2, 1));
    m2 = fmaxf(m2, __shfl_xor_sync(0xffffffffu, m2, 2));
    if ((lane & 3) == 0) { sRed[r1 * 4 + wn] = m1; sRed[r2 * 4 + wn] = m2; }
    __syncthreads();
    m1 = fmaxf(sRed[r1 * 4 + 0], sRed[r1 * 4 + 1]);
    m2 = fmaxf(sRed[r2 * 4 + 0], sRed[r2 * 4 + 1]);

    float s1 = 0.f, s2 = 0.f;
#pragma unroll
    for (int jt = 0; jt < 5; jt++)
#pragma unroll
        for (int n = 0; n < 4; n++) {
            float e0 = __expf(sc[jt][n][0] - m1);
            float e1 = __expf(sc[jt][n][1] - m1);
            float e2 = __expf(sc[jt][n][2] - m2);
            float e3 = __expf(sc[jt][n][3] - m2);
            sc[jt][n][0] = e0; sc[jt][n][1] = e1;
            sc[jt][n][2] = e2; sc[jt][n][3] = e3;
            s1 += e0 + e1; s2 += e2 + e3;
        }
    s1 += __shfl_xor_sync(0xffffffffu, s1, 1);
    s1 += __shfl_xor_sync(0xffffffffu, s1, 2);
    s2 += __shfl_xor_sync(0xffffffffu, s2, 1);
    s2 += __shfl_xor_sync(0xffffffffu, s2, 2);
    if ((lane & 3) == 0) { sRed[r1 * 4 + 2 + wn] = s1; sRed[r2 * 4 + 2 + wn] = s2; }
    __syncthreads();
    float inv1 = 1.f / (sRed[r1 * 4 + 2] + sRed[r1 * 4 + 3]);
    float inv2 = 1.f / (sRed[r2 * 4 + 2] + sRed[r2 * 4 + 3]);

    uint32_t ph[5][2][4], pl[5][2][4];
#pragma unroll
    for (int jt = 0; jt < 5; jt++)
#pragma unroll
        for (int t = 0; t < 2; t++) {
            pack2h(sc[jt][2*t][0] * inv1, sc[jt][2*t][1] * inv1,
                   ph[jt][t][0], pl[jt][t][0]);
            pack2h(sc[jt][2*t][2] * inv2, sc[jt][2*t][3] * inv2,
                   ph[jt][t][1], pl[jt][t][1]);
            pack2h(sc[jt][2*t+1][0] * inv1, sc[jt][2*t+1][1] * inv1,
                   ph[jt][t][2], pl[jt][t][2]);
            pack2h(sc[jt][2*t+1][2] * inv2, sc[jt][2*t+1][3] * inv2,
                   ph[jt][t][3], pl[jt][t][3]);
        }

    float oacc[8][4];
#pragma unroll
    for (int n = 0; n < 8; n++)
#pragma unroll
        for (int j = 0; j < 4; j++) oacc[n][j] = 0.f;

#pragma unroll
    for (int jt = 0; jt < 5; jt++) {
#pragma unroll
        for (int l = 0; l < 2; l++) {
            int e = tid + l * 256, row = e >> 3, c = e & 7;
            size_t vo = ((size_t)bh * 512 + i0 + jt * 64 + row) * 64 + c * 8;
            *(uint4*)(sma + 18432 + row * AT_LDB + c * 16) = *(const uint4*)&g_vh[vo];
            *(uint4*)(sma + 27648 + row * AT_LDB + c * 16) = *(const uint4*)&g_vl[vo];
        }
        __syncthreads();
#pragma unroll
        for (int t = 0; t < 2; t++) {
            uint32_t bfh[16], bfl[16];
            int g = lane >> 3;
            int kr = (g & 1) * 8 + (lane & 7);
            int nc = (g >> 1) * 8;
            uint32_t base = (uint32_t)((wn * 32 + t * 16 + kr) * AT_LDB + nc * 2);
#pragma unroll
            for (int dd = 0; dd < 4; dd++) {
                ldsm4t(&bfh[dd * 4], sKh + base + dd * 32);
                ldsm4t(&bfl[dd * 4], sKl + base + dd * 32);
            }
#pragma unroll
            for (int n = 0; n < 8; n++) {
                const uint32_t* bh_ = &bfh[(n >> 1) * 4 + (n & 1) * 2];
                const uint32_t* bl_ = &bfl[(n >> 1) * 4 + (n & 1) * 2];
                mma16816h(oacc[n], ph[jt][t], bh_);
                mma16816h(oacc[n], ph[jt][t], bl_);
                mma16816h(oacc[n], pl[jt][t], bh_);
            }
        }
        __syncthreads();
    }

    if (wn == 0) {
#pragma unroll
        for (int n = 0; n < 8; n++) {
            int c0 = n * 8 + (lane & 3) * 2;
            sO[r1 * 66 + c0]     = oacc[n][0];
            sO[r1 * 66 + c0 + 1] = oacc[n][1];
            sO[r2 * 66 + c0]     = oacc[n][2];
            sO[r2 * 66 + c0 + 1] = oacc[n][3];
        }
    }
    __syncthreads();
    if (wn == 1) {
#pragma unroll
        for (int n = 0; n < 8; n++) {
            int c0 = n * 8 + (lane & 3) * 2;
            float a0 = oacc[n][0] + sO[r1 * 66 + c0];
            float a1 = oacc[n][1] + sO[r1 * 66 + c0 + 1];
            float a2 = oacc[n][2] + sO[r2 * 66 + c0];
            float a3 = oacc[n][3] + sO[r2 * 66 + c0 + 1];
            uint32_t H, L;
            pack2h(a0, a1, H, L);
            size_t o1 = ((size_t)bb * 256 + i0 + r1) * 1024 + hh * 64 + c0;
            *(uint32_t*)&g_Oh[o1] = H; *(uint32_t*)&g_Ol[o1] = L;
            pack2h(a2, a3, H, L);
            size_t o2 = ((size_t)bb * 256 + i0 + r2) * 1024 + hh * 64 + c0;
            *(uint32_t*)&g_Oh[o2] = H; *(uint32_t*)&g_Ol[o2] = L;
        }
    }
}

// ============================================================================
// kernel_launch
// ============================================================================
extern "C" void kernel_launch(void* const* d_in, const int* in_sizes, int n_in,
                              void* d_out, int out_size)
{
    const float* x    = (const float*)d_in[0];
    const float* h    = (const float*)d_in[1];
    const float* Wqkv = (const float*)d_in[2];
    const float* Wkr  = (const float*)d_in[3];
    const float* R    = (const float*)d_in[4];
    const float* u    = (const float*)d_in[5];
    const float* v    = (const float*)d_in[6];
    const float* Wout = (const float*)d_in[7];
    float* out = (float*)d_out;

    __half *pAh, *pAl, *pB, *pBO, *pOh, *pOl;
    cudaGetSymbolAddress((void**)&pAh, g_Ah);
    cudaGetSymbolAddress((void**)&pAl, g_Al);
    cudaGetSymbolAddress((void**)&pB,  g_B);
    cudaGetSymbolAddress((void**)&pBO, g_BO);
    cudaGetSymbolAddress((void**)&pOh, g_Oh);
    cudaGetSymbolAddress((void**)&pOl, g_Ol);

    cudaFuncSetAttribute(mma_gemm, cudaFuncAttributeMaxDynamicSharedMemorySize,
                         MG_SMEM);

    // conversions
    conv_all_T<<<dim3(96, 32, 3), 256>>>(Wqkv, Wkr, Wout);
    conv_A<<<5120, 256>>>(x, h, R);

    // qkv GEMM (z=0, mode 1) + RW GEMM (z=1, mode 2) merged into one launch
    mma_gemm<<<dim3(12, 32, 2), 256, MG_SMEM>>>(pAh, pAl, pB, nullptr, 0, 1);

    // bias terms, then P (folds c + dt, writes padded -1e30 layout)
    cdterm<<<8706, 256>>>(u, v);
    p_gemm2<<<dim3(6, 4, 128), 256>>>();

    // fused attention
    attn_mma2<<<dim3(4, 128), 256>>>();

    // out = O @ Wout
    mma_gemm<<<dim3(4, 16, 1), 256, MG_SMEM>>>(pOh, pOl, pBO, out, 1024, 0);
}

// round 14
// speedup vs baseline: 1.2050x; 1.2050x over previous
#include <cuda_runtime.h>
#include <cuda_fp16.h>
#include <cstdint>

// ============================================================================
// B=8, N=256, M=256, T=512, H=16, D=64, DIM=1024.
// Window: j in [i, i+256]; delta = j-i; Ppad[bh][i][delta+64] holds
// 0.125*(q.RW + c + dt) for valid delta, -1e30 otherwise (q pre-scaled).
// Round 14: revert GEMM to round-12 config (measured 309us); merge conversion
// launches; move Ppad fill into cdterm launch.
// ============================================================================

__device__ __half g_RWh[1024u * 1024u];
__device__ __half g_RWl[1024u * 1024u];
__device__ __half g_qh[8u*16u*256u*64u], g_ql[8u*16u*256u*64u];
__device__ __half g_kh[8u*16u*512u*64u], g_kl[8u*16u*512u*64u];
__device__ __half g_vh[8u*16u*512u*64u], g_vl[8u*16u*512u*64u];
__device__ float g_Pp[8u * 16u * 256u * 384u];         // padded biased scores
__device__ float g_c [8u * 16u * 512u];
__device__ float g_dt[16u * 257u];

__device__ __half g_Ah [4096u * 1024u], g_Al [4096u * 1024u];  // cat(h,x) split
__device__ __half g_ARh[1024u * 1024u], g_ARl[1024u * 1024u];  // R split
__device__ __half g_B  [3072u * 1024u];                         // Wqkv^T single
__device__ __half g_BK [1024u * 1024u];                         // Wkr^T single
__device__ __half g_BO [1024u * 1024u];                         // Wout^T single
__device__ __half g_Oh [2048u * 1024u], g_Ol [2048u * 1024u];  // attn out split

// ============================================================================
// PTX helpers
// ============================================================================
__device__ __forceinline__ uint32_t smem_u32(const void* p) {
    uint32_t a;
    asm("{ .reg .u64 t; cvta.to.shared.u64 t, %1; cvt.u32.u64 %0, t; }"
        : "=r"(a) : "l"(p));
    return a;
}
__device__ __forceinline__ void cp16(uint32_t saddr, const void* g) {
    asm volatile("cp.async.cg.shared.global [%0], [%1], 16;"
                 :: "r"(saddr), "l"(g) : "memory");
}
#define CP_COMMIT() asm volatile("cp.async.commit_group;" ::: "memory")
#define CP_WAIT1()  asm volatile("cp.async.wait_group 1;" ::: "memory")
#define CP_WAIT0()  asm volatile("cp.async.wait_group 0;" ::: "memory")

__device__ __forceinline__ void ldsm4(uint32_t* r, uint32_t addr) {
    asm volatile("ldmatrix.sync.aligned.m8n8.x4.shared.b16 {%0,%1,%2,%3}, [%4];"
                 : "=r"(r[0]), "=r"(r[1]), "=r"(r[2]), "=r"(r[3]) : "r"(addr));
}
__device__ __forceinline__ void ldsm4t(uint32_t* r, uint32_t addr) {
    asm volatile("ldmatrix.sync.aligned.m8n8.x4.trans.shared.b16 {%0,%1,%2,%3}, [%4];"
                 : "=r"(r[0]), "=r"(r[1]), "=r"(r[2]), "=r"(r[3]) : "r"(addr));
}
// fp16 inputs, fp32 accumulate
__device__ __forceinline__ void mma16816h(float* c, const uint32_t* a,
                                          const uint32_t* b) {
    asm volatile(
        "mma.sync.aligned.m16n8k16.row.col.f32.f16.f16.f32 "
        "{%0,%1,%2,%3}, {%4,%5,%6,%7}, {%8,%9}, {%0,%1,%2,%3};"
        : "+f"(c[0]), "+f"(c[1]), "+f"(c[2]), "+f"(c[3])
        : "r"(a[0]), "r"(a[1]), "r"(a[2]), "r"(a[3]), "r"(b[0]), "r"(b[1]));
}

__device__ __forceinline__ unsigned short hbits(__half x) {
    return *reinterpret_cast<unsigned short*>(&x);
}
__device__ __forceinline__ void pack2h(float a, float b, uint32_t& H, uint32_t& L) {
    __half ah = __float2half_rn(a), bh = __float2half_rn(b);
    __half al = __float2half_rn(a - __half2float(ah));
    __half bl = __float2half_rn(b - __half2float(bh));
    H = (uint32_t)hbits(ah) | ((uint32_t)hbits(bh) << 16);
    L = (uint32_t)hbits(al) | ((uint32_t)hbits(bl) << 16);
}

// ============================================================================
// Dense mma GEMM (round-12 config, measured 309us total): CTA 128x128, BK=32,
// 2-stage cp.async, 80B smem rows, warp tile 64x32 (2x4 warps).
// A = fp16 hi/lo split, B = single fp16 -> 2 MMAs/tile.
// mode 0: fp32 C. mode 1: qkv scatter (q pre-scaled). mode 2: RW fp16 split.
// gridDim.z==2 merges the RW GEMM (z=1, 8x8 jobs) into the qkv launch (z=0).
// ============================================================================
#define MG_ARR 10240
#define MG_STG (3 * MG_ARR)              // Ah, Al, B
#define MG_SMEM (2 * MG_STG)             // 61440

__device__ __forceinline__ void qkv_scatter(int gr, int gc, float v0, float v1) {
    int b = gr >> 9, tt = gr & 511;
    int sec = gc >> 10, c2 = gc & 1023, hh = c2 >> 6, d = c2 & 63;
    if (sec == 0) {
        if (tt >= 256) {
            uint32_t H, L; pack2h(v0 * 0.125f, v1 * 0.125f, H, L);
            size_t o = (((size_t)b * 16 + hh) * 256 + (tt - 256)) * 64 + d;
            *(uint32_t*)&g_qh[o] = H; *(uint32_t*)&g_ql[o] = L;
        }
    } else {
        uint32_t H, L; pack2h(v0, v1, H, L);
        size_t o = (((size_t)b * 16 + hh) * 512 + tt) * 64 + d;
        if (sec == 1) { *(uint32_t*)&g_kh[o] = H; *(uint32_t*)&g_kl[o] = L; }
        else          { *(uint32_t*)&g_vh[o] = H; *(uint32_t*)&g_vl[o] = L; }
    }
}

__global__ __launch_bounds__(256, 2) void mma_gemm(
    const __half* __restrict__ Ah, const __half* __restrict__ Al,
    const __half* __restrict__ Bs,
    float* __restrict__ C, int ldc, int mode)
{
    int bx = blockIdx.x, by = blockIdx.y;
    if (blockIdx.z == 1) {
        if (bx >= 8 || by >= 8) return;      // merged RW GEMM: R @ Wkr
        Ah = g_ARh; Al = g_ARl; Bs = g_BK;
        mode = 2;
    } else {
        if (mode == 1 && bx < 8 && (by & 3) < 2) return;  // q for memory rows
    }

    extern __shared__ char smc[];
    uint32_t sb = smem_u32(smc);
    int tid = threadIdx.x, lane = tid & 31, wid = tid >> 5;
    int wm = wid >> 2, wn = wid & 3;

    const __half* gA[2] = { Ah, Al };

    // one stage = 1536 16B-chunks: 3 arrays x 128 rows x 4 chunks; 6/thread.
    auto load_stage = [&](int s, int kt) {
#pragma unroll
        for (int l = 0; l < 6; l++) {
            int idx = tid + l * 256;
            int arr = idx >> 9, e = idx & 511;
            int row = e >> 2, c = e & 3;
            const __half* gp = (arr < 2)
                ? gA[arr] + (size_t)(by * 128 + row) * 1024 + kt * 32 + c * 8
                : Bs + (size_t)(bx * 128 + row) * 1024 + kt * 32 + c * 8;
            cp16(sb + s * MG_STG + arr * MG_ARR + (uint32_t)(row * 80 + c * 16), gp);
        }
        CP_COMMIT();
    };

    float acc[16][4];
#pragma unroll
    for (int i = 0; i < 16; i++)
#pragma unroll
        for (int j = 0; j < 4; j++) acc[i][j] = 0.f;

    load_stage(0, 0);

    for (int kt = 0; kt < 32; kt++) {
        if (kt + 1 < 32) { load_stage((kt + 1) & 1, kt + 1); CP_WAIT1(); }
        else             { CP_WAIT0(); }
        __syncthreads();

        uint32_t stg = sb + (kt & 1) * MG_STG;
#pragma unroll
        for (int kk = 0; kk < 2; kk++) {
            uint32_t afh[4][4], afl[4][4];
            {
                int row = wm * 64 + (lane & 15);
                int c   = kk * 2 + (lane >> 4);
                uint32_t off = (uint32_t)(row * 80 + c * 16);
#pragma unroll
                for (int t = 0; t < 4; t++) {
                    ldsm4(afh[t], stg + 0 * MG_ARR + off + t * (16 * 80));
                    ldsm4(afl[t], stg + 1 * MG_ARR + off + t * (16 * 80));
                }
            }
            uint32_t bf[8];
            {
                int n = wn * 32 + ((lane >> 4) * 8 + (lane & 7));
                int c = kk * 2 + ((lane >> 3) & 1);
                uint32_t off = (uint32_t)(n * 80 + c * 16);
                ldsm4(&bf[0], stg + 2 * MG_ARR + off);
                ldsm4(&bf[4], stg + 2 * MG_ARR + off + 16 * 80);
            }
#pragma unroll
            for (int t = 0; t < 4; t++)
#pragma unroll
                for (int n = 0; n < 4; n++) {
                    float* cc = acc[t * 4 + n];
                    mma16816h(cc, afh[t], &bf[n * 2]);
                    mma16816h(cc, afl[t], &bf[n * 2]);
                }
        }
        __syncthreads();
    }

#pragma unroll
    for (int t = 0; t < 4; t++)
#pragma unroll
        for (int n = 0; n < 4; n++) {
            int gr = by * 128 + wm * 64 + t * 16 + (lane >> 2);
            int gc = bx * 128 + wn * 32 + n * 8 + (lane & 3) * 2;
            float* cc = acc[t * 4 + n];
            if (mode == 0) {
                *(float2*)&C[(size_t)gr * ldc + gc]       = make_float2(cc[0], cc[1]);
                *(float2*)&C[(size_t)(gr + 8) * ldc + gc] = make_float2(cc[2], cc[3]);
            } else if (mode == 2) {
                uint32_t H, L;
                pack2h(cc[0], cc[1], H, L);
                *(uint32_t*)&g_RWh[(size_t)gr * 1024 + gc] = H;
                *(uint32_t*)&g_RWl[(size_t)gr * 1024 + gc] = L;
                pack2h(cc[2], cc[3], H, L);
                *(uint32_t*)&g_RWh[(size_t)(gr + 8) * 1024 + gc] = H;
                *(uint32_t*)&g_RWl[(size_t)(gr + 8) * 1024 + gc] = L;
            } else {
                qkv_scatter(gr, gc, cc[0], cc[1]);
                qkv_scatter(gr + 8, gc, cc[2], cc[3]);
            }
        }
}

// ============================================================================
// Conversions — single launch. z=0: Wqkv^T, z=1: Wkr^T, z=2: Wout^T,
// z=3: cat(h,x) + R activation splits (grid-stride over 5120 chunk-blocks).
// ============================================================================
__device__ __forceinline__ void split4h(float4 v, uint2& H, uint2& L) {
    uint32_t h0, l0, h1, l1;
    pack2h(v.x, v.y, h0, l0);
    pack2h(v.z, v.w, h1, l1);
    H.x = h0; H.y = h1; L.x = l0; L.y = l1;
}

__global__ __launch_bounds__(256) void conv_all(
    const float* __restrict__ Wqkv, const float* __restrict__ Wkr,
    const float* __restrict__ Wout,
    const float* __restrict__ x, const float* __restrict__ h,
    const float* __restrict__ R)
{
    int z = blockIdx.z;
    if (z == 3) {
        int lb = blockIdx.x + blockIdx.y * 96;   // 0..3071
#pragma unroll
        for (int r = 0; r < 2; r++) {
            int blk = lb * 2 + r;
            if (blk >= 5120) break;
            if (blk < 4096) {
                int i = blk * 256 + threadIdx.x;
                int row = i >> 8, c4 = i & 255;
                int b = row >> 9, t = row & 511;
                const float4* src = (const float4*)((t < 256)
                    ? (h + ((size_t)b * 256 + t) * 1024)
                    : (x + ((size_t)b * 256 + (t - 256)) * 1024));
                uint2 H, L;
                split4h(src[c4], H, L);
                ((uint2*)g_Ah)[i] = H; ((uint2*)g_Al)[i] = L;
            } else {
                int i = (blk - 4096) * 256 + threadIdx.x;
                uint2 H, L;
                split4h(((const float4*)R)[i], H, L);
                ((uint2*)g_ARh)[i] = H; ((uint2*)g_ARl)[i] = L;
            }
        }
        return;
    }

    const float* W; __half* Th; int N;
    if (z == 0)      { W = Wqkv; Th = g_B;  N = 3072; }
    else if (z == 1) { if (blockIdx.x >= 32) return; W = Wkr;  Th = g_BK; N = 1024; }
    else             { if (blockIdx.x >= 32) return; W = Wout; Th = g_BO; N = 1024; }

    __shared__ float ts[32][33];
    int n0 = blockIdx.x * 32, k0 = blockIdx.y * 32;
    int tx = threadIdx.x & 31, ty = threadIdx.x >> 5;
#pragma unroll
    for (int r = 0; r < 32; r += 8)
        ts[ty + r][tx] = W[(size_t)(k0 + ty + r) * N + n0 + tx];
    __syncthreads();
#pragma unroll
    for (int r = 0; r < 32; r += 8) {
        float v = ts[tx][ty + r];
        Th[(size_t)(n0 + ty + r) * 1024 + k0 + tx] = __float2half_rn(v);
    }
}

// cterm (blocks 0..8191) + dterm (8192..8705) + Ppad idx<64 fill (8706..9217)
__global__ __launch_bounds__(256) void cdterm(const float* __restrict__ u,
                                              const float* __restrict__ v)
{
    int blk = blockIdx.x;
    int lane = threadIdx.x & 31;
    if (blk < 8192) {
        int row = blk * 8 + (threadIdx.x >> 5);
        size_t o = (size_t)row * 64 + lane;
        float k0 = __half2float(g_kh[o]) + __half2float(g_kl[o]);
        float k1 = __half2float(g_kh[o + 32]) + __half2float(g_kl[o + 32]);
        float s = u[lane] * k0 + u[lane + 32] * k1;
#pragma unroll
        for (int of = 16; of; of >>= 1) s += __shfl_xor_sync(0xffffffffu, s, of);
        if (lane == 0) g_c[row] = s;
    } else if (blk < 8706) {
        int row = (blk - 8192) * 8 + (threadIdx.x >> 5);
        if (row >= 16 * 257) return;
        int hh = row / 257, t = row % 257;
        size_t base = (size_t)((t + 768) & 1023) * 1024 + hh * 64;
        float r0 = __half2float(g_RWh[base + lane]) + __half2float(g_RWl[base + lane]);
        float r1 = __half2float(g_RWh[base + lane + 32])
                 + __half2float(g_RWl[base + lane + 32]);
        float s = v[lane] * r0 + v[lane + 32] * r1;
#pragma unroll
        for (int of = 16; of; of >>= 1) s += __shfl_xor_sync(0xffffffffu, s, of);
        if (lane == 0) g_dt[row] = s;
    } else {
        // Ppad fill: idx in [0,64) <- -1e30 for one (bh, i-tile)
        int fid = blk - 8706;                // 0..511
        int bh = fid >> 2, it = fid & 3;
        int i0 = it * 64;
        float4 neg = make_float4(-1e30f, -1e30f, -1e30f, -1e30f);
#pragma unroll
        for (int l = 0; l < 4; l++) {
            int e = threadIdx.x + l * 256;   // 0..1023
            int row = e >> 4, f4 = e & 15;
            *(float4*)&g_Pp[((size_t)bh * 256 + i0 + row) * 384 + f4 * 4] = neg;
        }
    }
}

// ============================================================================
// P GEMM -> Ppad[bh][i][idx], idx = delta + 64 in [0,384). fp16 3-MMA.
// grid (5 t-tiles, 4 i-tiles, 128 bh); fill handled by cdterm.
// ============================================================================
#define PG_LDB 144
__global__ __launch_bounds__(256) void p_gemm2()
{
    __shared__ char sm2[4 * 64 * PG_LDB];
    int tt = blockIdx.x, it = blockIdx.y, bh = blockIdx.z;
    int hh = bh & 15;
    int i0 = it * 64;
    int tid = threadIdx.x, lane = tid & 31, wid = tid >> 5;

    uint32_t sb = smem_u32(sm2);
    uint32_t sQh = sb, sQl = sb + 9216, sBh = sb + 18432, sBl = sb + 27648;
    int wm = wid >> 1, wn = wid & 1;

#pragma unroll
    for (int l = 0; l < 2; l++) {
        int e = tid + l * 256;
        int row = e >> 3, c = e & 7;
        size_t qo = ((size_t)bh * 256 + i0 + row) * 64 + c * 8;
        *(uint4*)(sm2 + row * PG_LDB + c * 16) = *(const uint4*)&g_qh[qo];
        *(uint4*)(sm2 + 9216 + row * PG_LDB + c * 16) = *(const uint4*)&g_ql[qo];
        int t = tt * 64 + row;
        int rr = (t + 768) & 1023;
        size_t bo = (size_t)rr * 1024 + hh * 64 + c * 8;
        *(uint4*)(sm2 + 18432 + row * PG_LDB + c * 16) = *(const uint4*)&g_RWh[bo];
        *(uint4*)(sm2 + 27648 + row * PG_LDB + c * 16) = *(const uint4*)&g_RWl[bo];
    }
    __syncthreads();

    float acc[4][4];
#pragma unroll
    for (int n = 0; n < 4; n++)
#pragma unroll
        for (int j = 0; j < 4; j++) acc[n][j] = 0.f;

#pragma unroll
    for (int kk = 0; kk < 4; kk++) {
        uint32_t afh[4], afl[4];
        {
            int row = wm * 16 + (lane & 15);
            uint32_t off = (uint32_t)(row * PG_LDB + kk * 32 + (lane >> 4) * 16);
            ldsm4(afh, sQh + off);
            ldsm4(afl, sQl + off);
        }
        uint32_t bfh[8], bfl[8];
        {
            int n = wn * 32 + ((lane >> 4) * 8 + (lane & 7));
            uint32_t off = (uint32_t)(n * PG_LDB + kk * 32 + ((lane >> 3) & 1) * 16);
            ldsm4(&bfh[0], sBh + off);
            ldsm4(&bfh[4], sBh + off + 16 * PG_LDB);
            ldsm4(&bfl[0], sBl + off);
            ldsm4(&bfl[4], sBl + off + 16 * PG_LDB);
        }
#pragma unroll
        for (int n = 0; n < 4; n++) {
            mma16816h(acc[n], afh, &bfh[n * 2]);
            mma16816h(acc[n], afh, &bfl[n * 2]);
            mma16816h(acc[n], afl, &bfh[n * 2]);
        }
    }

#pragma unroll
    for (int n = 0; n < 4; n++) {
        int tl = wn * 32 + n * 8 + (lane & 3) * 2;
#pragma unroll
        for (int half = 0; half < 2; half++) {
            int ii = i0 + wm * 16 + (lane >> 2) + half * 8;
#pragma unroll
            for (int e = 0; e < 2; e++) {
                int t = tt * 64 + tl + e;
                float a = acc[n][half * 2 + e];
                float val = -1e30f;
                if (t < 257)
                    val = a + 0.125f * (g_c[(size_t)bh * 512 + ii + t]
                                        + g_dt[hh * 257 + t]);
                g_Pp[((size_t)bh * 256 + ii) * 384 + t + 64] = val;
            }
        }
    }
}

// ============================================================================
// Fused attention (register softmax), fp16 3-MMA
// ============================================================================
#define AT_LDB 144
__global__ __launch_bounds__(256) void attn_mma2()
{
    __shared__ char sma[36864 + 1024];
    uint32_t sb = smem_u32(sma);
    uint32_t sQh = sb, sQl = sb + 9216;
    uint32_t sKh = sb + 18432, sKl = sb + 27648;
    float* sRed = (float*)(sma + 36864);
    float* sO   = (float*)sma;

    int it = blockIdx.x, bh = blockIdx.y;
    int hh = bh & 15, bb = bh >> 4;
    int i0 = it * 64;
    int tid = threadIdx.x, lane = tid & 31, wid = tid >> 5;
    int wm = wid >> 1, wn = wid & 1;

#pragma unroll
    for (int l = 0; l < 2; l++) {
        int e = tid + l * 256, row = e >> 3, c = e & 7;
        size_t qo = ((size_t)bh * 256 + i0 + row) * 64 + c * 8;
        *(uint4*)(sma + row * AT_LDB + c * 16) = *(const uint4*)&g_qh[qo];
        *(uint4*)(sma + 9216 + row * AT_LDB + c * 16) = *(const uint4*)&g_ql[qo];
    }

    float sc[5][4][4];
#pragma unroll
    for (int jt = 0; jt < 5; jt++)
#pragma unroll
        for (int n = 0; n < 4; n++)
#pragma unroll
            for (int j = 0; j < 4; j++) sc[jt][n][j] = 0.f;

#pragma unroll
    for (int jt = 0; jt < 5; jt++) {
#pragma unroll
        for (int l = 0; l < 2; l++) {
            int e = tid + l * 256, row = e >> 3, c = e & 7;
            size_t ko = ((size_t)bh * 512 + i0 + jt * 64 + row) * 64 + c * 8;
            *(uint4*)(sma + 18432 + row * AT_LDB + c * 16) = *(const uint4*)&g_kh[ko];
            *(uint4*)(sma + 27648 + row * AT_LDB + c * 16) = *(const uint4*)&g_kl[ko];
        }
        __syncthreads();
#pragma unroll
        for (int kk = 0; kk < 4; kk++) {
            uint32_t afh[4], afl[4];
            {
                int row = wm * 16 + (lane & 15);
                uint32_t off = (uint32_t)(row * AT_LDB + kk * 32 + (lane >> 4) * 16);
                ldsm4(afh, sQh + off);
                ldsm4(afl, sQl + off);
            }
            uint32_t bfh[8], bfl[8];
            {
                int n = wn * 32 + ((lane >> 4) * 8 + (lane & 7));
                uint32_t off = (uint32_t)(n * AT_LDB + kk * 32 + ((lane >> 3) & 1) * 16);
                ldsm4(&bfh[0], sKh + off);
                ldsm4(&bfh[4], sKh + off + 16 * AT_LDB);
                ldsm4(&bfl[0], sKl + off);
                ldsm4(&bfl[4], sKl + off + 16 * AT_LDB);
            }
#pragma unroll
            for (int n = 0; n < 4; n++) {
                mma16816h(sc[jt][n], afh, &bfh[n * 2]);
                mma16816h(sc[jt][n], afh, &bfl[n * 2]);
                mma16816h(sc[jt][n], afl, &bfh[n * 2]);
            }
        }
        __syncthreads();
    }

    int r1 = wm * 16 + (lane >> 2), r2 = r1 + 8;
    const float* P1 = &g_Pp[((size_t)bh * 256 + i0 + r1) * 384 + 64 - r1];
    const float* P2 = &g_Pp[((size_t)bh * 256 + i0 + r2) * 384 + 64 - r2];
    float m1 = -1e30f, m2 = -1e30f;
#pragma unroll
    for (int jt = 0; jt < 5; jt++)
#pragma unroll
        for (int n = 0; n < 4; n++) {
            int col = jt * 64 + wn * 32 + n * 8 + (lane & 3) * 2;
            sc[jt][n][0] += P1[col];     sc[jt][n][1] += P1[col + 1];
            sc[jt][n][2] += P2[col];     sc[jt][n][3] += P2[col + 1];
            m1 = fmaxf(m1, fmaxf(sc[jt][n][0], sc[jt][n][1]));
            m2 = fmaxf(m2, fmaxf(sc[jt][n][2], sc[jt][n][3]));
        }
    m1 = fmaxf(m1, __shfl_xor_sync(0xffffffffu, m1, 1));
    m1 = fmaxf(m1, __shfl_xor_sync(0xffffffffu, m1, 2));
    m2 = fmaxf(m2, __shfl_xor_sync(0xffffffffu, m2, 1));
    m2 = fmaxf(m2, __shfl_xor_sync(0xffffffffu, m2, 2));
    if ((lane & 3) == 0) { sRed[r1 * 4 + wn] = m1; sRed[r2 * 4 + wn] = m2; }
    __syncthreads();
    m1 = fmaxf(sRed[r1 * 4 + 0], sRed[r1 * 4 + 1]);
    m2 = fmaxf(sRed[r2 * 4 + 0], sRed[r2 * 4 + 1]);

    float s1 = 0.f, s2 = 0.f;
#pragma unroll
    for (int jt = 0; jt < 5; jt++)
#pragma unroll
        for (int n = 0; n < 4; n++) {
            float e0 = __expf(sc[jt][n][0] - m1);
            float e1 = __expf(sc[jt][n][1] - m1);
            float e2 = __expf(sc[jt][n][2] - m2);
            float e3 = __expf(sc[jt][n][3] - m2);
            sc[jt][n][0] = e0; sc[jt][n][1] = e1;
            sc[jt][n][2] = e2; sc[jt][n][3] = e3;
            s1 += e0 + e1; s2 += e2 + e3;
        }
    s1 += __shfl_xor_sync(0xffffffffu, s1, 1);
    s1 += __shfl_xor_sync(0xffffffffu, s1, 2);
    s2 += __shfl_xor_sync(0xffffffffu, s2, 1);
    s2 += __shfl_xor_sync(0xffffffffu, s2, 2);
    if ((lane & 3) == 0) { sRed[r1 * 4 + 2 + wn] = s1; sRed[r2 * 4 + 2 + wn] = s2; }
    __syncthreads();
    float inv1 = 1.f / (sRed[r1 * 4 + 2] + sRed[r1 * 4 + 3]);
    float inv2 = 1.f / (sRed[r2 * 4 + 2] + sRed[r2 * 4 + 3]);

    uint32_t ph[5][2][4], pl[5][2][4];
#pragma unroll
    for (int jt = 0; jt < 5; jt++)
#pragma unroll
        for (int t = 0; t < 2; t++) {
            pack2h(sc[jt][2*t][0] * inv1, sc[jt][2*t][1] * inv1,
                   ph[jt][t][0], pl[jt][t][0]);
            pack2h(sc[jt][2*t][2] * inv2, sc[jt][2*t][3] * inv2,
                   ph[jt][t][1], pl[jt][t][1]);
            pack2h(sc[jt][2*t+1][0] * inv1, sc[jt][2*t+1][1] * inv1,
                   ph[jt][t][2], pl[jt][t][2]);
            pack2h(sc[jt][2*t+1][2] * inv2, sc[jt][2*t+1][3] * inv2,
                   ph[jt][t][3], pl[jt][t][3]);
        }

    float oacc[8][4];
#pragma unroll
    for (int n = 0; n < 8; n++)
#pragma unroll
        for (int j = 0; j < 4; j++) oacc[n][j] = 0.f;

#pragma unroll
    for (int jt = 0; jt < 5; jt++) {
#pragma unroll
        for (int l = 0; l < 2; l++) {
            int e = tid + l * 256, row = e >> 3, c = e & 7;
            size_t vo = ((size_t)bh * 512 + i0 + jt * 64 + row) * 64 + c * 8;
            *(uint4*)(sma + 18432 + row * AT_LDB + c * 16) = *(const uint4*)&g_vh[vo];
            *(uint4*)(sma + 27648 + row * AT_LDB + c * 16) = *(const uint4*)&g_vl[vo];
        }
        __syncthreads();
#pragma unroll
        for (int t = 0; t < 2; t++) {
            uint32_t bfh[16], bfl[16];
            int g = lane >> 3;
            int kr = (g & 1) * 8 + (lane & 7);
            int nc = (g >> 1) * 8;
            uint32_t base = (uint32_t)((wn * 32 + t * 16 + kr) * AT_LDB + nc * 2);
#pragma unroll
            for (int dd = 0; dd < 4; dd++) {
                ldsm4t(&bfh[dd * 4], sKh + base + dd * 32);
                ldsm4t(&bfl[dd * 4], sKl + base + dd * 32);
            }
#pragma unroll
            for (int n = 0; n < 8; n++) {
                const uint32_t* bh_ = &bfh[(n >> 1) * 4 + (n & 1) * 2];
                const uint32_t* bl_ = &bfl[(n >> 1) * 4 + (n & 1) * 2];
                mma16816h(oacc[n], ph[jt][t], bh_);
                mma16816h(oacc[n], ph[jt][t], bl_);
                mma16816h(oacc[n], pl[jt][t], bh_);
            }
        }
        __syncthreads();
    }

    if (wn == 0) {
#pragma unroll
        for (int n = 0; n < 8; n++) {
            int c0 = n * 8 + (lane & 3) * 2;
            sO[r1 * 66 + c0]     = oacc[n][0];
            sO[r1 * 66 + c0 + 1] = oacc[n][1];
            sO[r2 * 66 + c0]     = oacc[n][2];
            sO[r2 * 66 + c0 + 1] = oacc[n][3];
        }
    }
    __syncthreads();
    if (wn == 1) {
#pragma unroll
        for (int n = 0; n < 8; n++) {
            int c0 = n * 8 + (lane & 3) * 2;
            float a0 = oacc[n][0] + sO[r1 * 66 + c0];
            float a1 = oacc[n][1] + sO[r1 * 66 + c0 + 1];
            float a2 = oacc[n][2] + sO[r2 * 66 + c0];
            float a3 = oacc[n][3] + sO[r2 * 66 + c0 + 1];
            uint32_t H, L;
            pack2h(a0, a1, H, L);
            size_t o1 = ((size_t)bb * 256 + i0 + r1) * 1024 + hh * 64 + c0;
            *(uint32_t*)&g_Oh[o1] = H; *(uint32_t*)&g_Ol[o1] = L;
            pack2h(a2, a3, H, L);
            size_t o2 = ((size_t)bb * 256 + i0 + r2) * 1024 + hh * 64 + c0;
            *(uint32_t*)&g_Oh[o2] = H; *(uint32_t*)&g_Ol[o2] = L;
        }
    }
}

// ============================================================================
// kernel_launch
// ============================================================================
extern "C" void kernel_launch(void* const* d_in, const int* in_sizes, int n_in,
                              void* d_out, int out_size)
{
    const float* x    = (const float*)d_in[0];
    const float* h    = (const float*)d_in[1];
    const float* Wqkv = (const float*)d_in[2];
    const float* Wkr  = (const float*)d_in[3];
    const float* R    = (const float*)d_in[4];
    const float* u    = (const float*)d_in[5];
    const float* v    = (const float*)d_in[6];
    const float* Wout = (const float*)d_in[7];
    float* out = (float*)d_out;

    __half *pAh, *pAl, *pB, *pBO, *pOh, *pOl;
    cudaGetSymbolAddress((void**)&pAh, g_Ah);
    cudaGetSymbolAddress((void**)&pAl, g_Al);
    cudaGetSymbolAddress((void**)&pB,  g_B);
    cudaGetSymbolAddress((void**)&pBO, g_BO);
    cudaGetSymbolAddress((void**)&pOh, g_Oh);
    cudaGetSymbolAddress((void**)&pOl, g_Ol);

    cudaFuncSetAttribute(mma_gemm, cudaFuncAttributeMaxDynamicSharedMemorySize,
                         MG_SMEM);

    // all conversions in one launch
    conv_all<<<dim3(96, 32, 4), 256>>>(Wqkv, Wkr, Wout, x, h, R);

    // qkv GEMM (z=0, mode 1) + RW GEMM (z=1, mode 2) merged into one launch
    mma_gemm<<<dim3(24, 32, 2), 256, MG_SMEM>>>(pAh, pAl, pB, nullptr, 0, 1);

    // bias terms + Ppad fill, then P (folds c + dt)
    cdterm<<<9218, 256>>>(u, v);
    p_gemm2<<<dim3(5, 4, 128), 256>>>();

    // fused attention
    attn_mma2<<<dim3(4, 128), 256>>>();

    // out = O @ Wout
    mma_gemm<<<dim3(8, 16, 1), 256, MG_SMEM>>>(pOh, pOl, pBO, out, 1024, 0);
}

// round 17
// speedup vs baseline: 1.4422x; 1.1968x over previous
#include <cuda_runtime.h>
#include <cuda_fp16.h>
#include <cstdint>

// ============================================================================
// B=8, N=256, M=256, T=512, H=16, D=64, DIM=1024.
// Window: j in [i, i+256]; delta = j-i; Ppad[bh][i][delta+64] holds
// 0.125*(q.RW + c + dt) for valid delta, -1e30 otherwise (q pre-scaled).
// Round 15: qkv/RW GEMM A -> single fp16 (1 MMA/tile); out GEMM keeps split
// A (2 MMA). p_gemm2 v3: one block per (it,bh), loops 5 t-tiles (q loaded 1x).
// ============================================================================

__device__ __half g_RWh[1024u * 1024u];
__device__ __half g_RWl[1024u * 1024u];
__device__ __half g_qh[8u*16u*256u*64u], g_ql[8u*16u*256u*64u];
__device__ __half g_kh[8u*16u*512u*64u], g_kl[8u*16u*512u*64u];
__device__ __half g_vh[8u*16u*512u*64u], g_vl[8u*16u*512u*64u];
__device__ float g_Pp[8u * 16u * 256u * 384u];         // padded biased scores
__device__ float g_c [8u * 16u * 512u];
__device__ float g_dt[16u * 257u];

__device__ __half g_A  [4096u * 1024u];                // cat(h,x) single fp16
__device__ __half g_AR [1024u * 1024u];                // R single fp16
__device__ __half g_B  [3072u * 1024u];                // Wqkv^T single
__device__ __half g_BK [1024u * 1024u];                // Wkr^T single
__device__ __half g_BO [1024u * 1024u];                // Wout^T single
__device__ __half g_Oh [2048u * 1024u], g_Ol [2048u * 1024u];  // attn out split

// ============================================================================
// PTX helpers
// ============================================================================
__device__ __forceinline__ uint32_t smem_u32(const void* p) {
    uint32_t a;
    asm("{ .reg .u64 t; cvta.to.shared.u64 t, %1; cvt.u32.u64 %0, t; }"
        : "=r"(a) : "l"(p));
    return a;
}
__device__ __forceinline__ void cp16(uint32_t saddr, const void* g) {
    asm volatile("cp.async.cg.shared.global [%0], [%1], 16;"
                 :: "r"(saddr), "l"(g) : "memory");
}
#define CP_COMMIT() asm volatile("cp.async.commit_group;" ::: "memory")
#define CP_WAIT1()  asm volatile("cp.async.wait_group 1;" ::: "memory")
#define CP_WAIT0()  asm volatile("cp.async.wait_group 0;" ::: "memory")

__device__ __forceinline__ void ldsm4(uint32_t* r, uint32_t addr) {
    asm volatile("ldmatrix.sync.aligned.m8n8.x4.shared.b16 {%0,%1,%2,%3}, [%4];"
                 : "=r"(r[0]), "=r"(r[1]), "=r"(r[2]), "=r"(r[3]) : "r"(addr));
}
__device__ __forceinline__ void ldsm4t(uint32_t* r, uint32_t addr) {
    asm volatile("ldmatrix.sync.aligned.m8n8.x4.trans.shared.b16 {%0,%1,%2,%3}, [%4];"
                 : "=r"(r[0]), "=r"(r[1]), "=r"(r[2]), "=r"(r[3]) : "r"(addr));
}
// fp16 inputs, fp32 accumulate
__device__ __forceinline__ void mma16816h(float* c, const uint32_t* a,
                                          const uint32_t* b) {
    asm volatile(
        "mma.sync.aligned.m16n8k16.row.col.f32.f16.f16.f32 "
        "{%0,%1,%2,%3}, {%4,%5,%6,%7}, {%8,%9}, {%0,%1,%2,%3};"
        : "+f"(c[0]), "+f"(c[1]), "+f"(c[2]), "+f"(c[3])
        : "r"(a[0]), "r"(a[1]), "r"(a[2]), "r"(a[3]), "r"(b[0]), "r"(b[1]));
}

__device__ __forceinline__ unsigned short hbits(__half x) {
    return *reinterpret_cast<unsigned short*>(&x);
}
__device__ __forceinline__ void pack2h(float a, float b, uint32_t& H, uint32_t& L) {
    __half ah = __float2half_rn(a), bh = __float2half_rn(b);
    __half al = __float2half_rn(a - __half2float(ah));
    __half bl = __float2half_rn(b - __half2float(bh));
    H = (uint32_t)hbits(ah) | ((uint32_t)hbits(bh) << 16);
    L = (uint32_t)hbits(al) | ((uint32_t)hbits(bl) << 16);
}
__device__ __forceinline__ uint32_t pack2s(float a, float b) {
    return (uint32_t)hbits(__float2half_rn(a))
         | ((uint32_t)hbits(__float2half_rn(b)) << 16);
}

__device__ __forceinline__ void qkv_scatter(int gr, int gc, float v0, float v1) {
    int b = gr >> 9, tt = gr & 511;
    int sec = gc >> 10, c2 = gc & 1023, hh = c2 >> 6, d = c2 & 63;
    if (sec == 0) {
        if (tt >= 256) {
            uint32_t H, L; pack2h(v0 * 0.125f, v1 * 0.125f, H, L);
            size_t o = (((size_t)b * 16 + hh) * 256 + (tt - 256)) * 64 + d;
            *(uint32_t*)&g_qh[o] = H; *(uint32_t*)&g_ql[o] = L;
        }
    } else {
        uint32_t H, L; pack2h(v0, v1, H, L);
        size_t o = (((size_t)b * 16 + hh) * 512 + tt) * 64 + d;
        if (sec == 1) { *(uint32_t*)&g_kh[o] = H; *(uint32_t*)&g_kl[o] = L; }
        else          { *(uint32_t*)&g_vh[o] = H; *(uint32_t*)&g_vl[o] = L; }
    }
}

// ============================================================================
// qkv/RW GEMM: single-fp16 A x single-fp16 B, 1 MMA/tile. CTA 128x128, BK=32,
// 2-stage cp.async, 80B smem rows, warp tile 64x32 (2x4 warps).
// mode 1: qkv scatter. z==1: merged RW GEMM (mode 2, fp16-split output).
// ============================================================================
#define M1_ARR 10240
#define M1_STG (2 * M1_ARR)              // A, B
#define M1_SMEM (2 * M1_STG)             // 40960

__global__ __launch_bounds__(256, 2) void mma_gemm1(
    const __half* __restrict__ As, const __half* __restrict__ Bs, int mode)
{
    int bx = blockIdx.x, by = blockIdx.y;
    if (blockIdx.z == 1) {
        if (bx >= 8 || by >= 8) return;      // merged RW GEMM: R @ Wkr
        As = g_AR; Bs = g_BK;
        mode = 2;
    } else {
        if (bx < 8 && (by & 3) < 2) return;  // q for memory rows: unused
    }

    extern __shared__ char smc[];
    uint32_t sb = smem_u32(smc);
    int tid = threadIdx.x, lane = tid & 31, wid = tid >> 5;
    int wm = wid >> 2, wn = wid & 3;

    // one stage = 1024 16B-chunks: 2 arrays x 128 rows x 4 chunks; 4/thread.
    auto load_stage = [&](int s, int kt) {
#pragma unroll
        for (int l = 0; l < 4; l++) {
            int idx = tid + l * 256;
            int arr = idx >> 9, e = idx & 511;
            int row = e >> 2, c = e & 3;
            const __half* gp = (arr == 0)
                ? As + (size_t)(by * 128 + row) * 1024 + kt * 32 + c * 8
                : Bs + (size_t)(bx * 128 + row) * 1024 + kt * 32 + c * 8;
            cp16(sb + s * M1_STG + arr * M1_ARR + (uint32_t)(row * 80 + c * 16), gp);
        }
        CP_COMMIT();
    };

    float acc[16][4];
#pragma unroll
    for (int i = 0; i < 16; i++)
#pragma unroll
        for (int j = 0; j < 4; j++) acc[i][j] = 0.f;

    load_stage(0, 0);

    for (int kt = 0; kt < 32; kt++) {
        if (kt + 1 < 32) { load_stage((kt + 1) & 1, kt + 1); CP_WAIT1(); }
        else             { CP_WAIT0(); }
        __syncthreads();

        uint32_t stg = sb + (kt & 1) * M1_STG;
#pragma unroll
        for (int kk = 0; kk < 2; kk++) {
            uint32_t af[4][4];
            {
                int row = wm * 64 + (lane & 15);
                int c   = kk * 2 + (lane >> 4);
                uint32_t off = (uint32_t)(row * 80 + c * 16);
#pragma unroll
                for (int t = 0; t < 4; t++)
                    ldsm4(af[t], stg + 0 * M1_ARR + off + t * (16 * 80));
            }
            uint32_t bf[8];
            {
                int n = wn * 32 + ((lane >> 4) * 8 + (lane & 7));
                int c = kk * 2 + ((lane >> 3) & 1);
                uint32_t off = (uint32_t)(n * 80 + c * 16);
                ldsm4(&bf[0], stg + 1 * M1_ARR + off);
                ldsm4(&bf[4], stg + 1 * M1_ARR + off + 16 * 80);
            }
#pragma unroll
            for (int t = 0; t < 4; t++)
#pragma unroll
                for (int n = 0; n < 4; n++)
                    mma16816h(acc[t * 4 + n], af[t], &bf[n * 2]);
        }
        __syncthreads();
    }

#pragma unroll
    for (int t = 0; t < 4; t++)
#pragma unroll
        for (int n = 0; n < 4; n++) {
            int gr = by * 128 + wm * 64 + t * 16 + (lane >> 2);
            int gc = bx * 128 + wn * 32 + n * 8 + (lane & 3) * 2;
            float* cc = acc[t * 4 + n];
            if (mode == 2) {
                uint32_t H, L;
                pack2h(cc[0], cc[1], H, L);
                *(uint32_t*)&g_RWh[(size_t)gr * 1024 + gc] = H;
                *(uint32_t*)&g_RWl[(size_t)gr * 1024 + gc] = L;
                pack2h(cc[2], cc[3], H, L);
                *(uint32_t*)&g_RWh[(size_t)(gr + 8) * 1024 + gc] = H;
                *(uint32_t*)&g_RWl[(size_t)(gr + 8) * 1024 + gc] = L;
            } else {
                qkv_scatter(gr, gc, cc[0], cc[1]);
                qkv_scatter(gr + 8, gc, cc[2], cc[3]);
            }
        }
}

// ============================================================================
// out GEMM: split-A (O hi/lo) x single B -> fp32 C. Round-12 config (2 MMA).
// ============================================================================
#define MG_ARR 10240
#define MG_STG (3 * MG_ARR)
#define MG_SMEM (2 * MG_STG)             // 61440

__global__ __launch_bounds__(256, 2) void mma_gemm_out(
    const __half* __restrict__ Ah, const __half* __restrict__ Al,
    const __half* __restrict__ Bs, float* __restrict__ C, int ldc)
{
    int bx = blockIdx.x, by = blockIdx.y;
    extern __shared__ char smc2[];
    uint32_t sb = smem_u32(smc2);
    int tid = threadIdx.x, lane = tid & 31, wid = tid >> 5;
    int wm = wid >> 2, wn = wid & 3;

    const __half* gA[2] = { Ah, Al };

    auto load_stage = [&](int s, int kt) {
#pragma unroll
        for (int l = 0; l < 6; l++) {
            int idx = tid + l * 256;
            int arr = idx >> 9, e = idx & 511;
            int row = e >> 2, c = e & 3;
            const __half* gp = (arr < 2)
                ? gA[arr] + (size_t)(by * 128 + row) * 1024 + kt * 32 + c * 8
                : Bs + (size_t)(bx * 128 + row) * 1024 + kt * 32 + c * 8;
            cp16(sb + s * MG_STG + arr * MG_ARR + (uint32_t)(row * 80 + c * 16), gp);
        }
        CP_COMMIT();
    };

    float acc[16][4];
#pragma unroll
    for (int i = 0; i < 16; i++)
#pragma unroll
        for (int j = 0; j < 4; j++) acc[i][j] = 0.f;

    load_stage(0, 0);

    for (int kt = 0; kt < 32; kt++) {
        if (kt + 1 < 32) { load_stage((kt + 1) & 1, kt + 1); CP_WAIT1(); }
        else             { CP_WAIT0(); }
        __syncthreads();

        uint32_t stg = sb + (kt & 1) * MG_STG;
#pragma unroll
        for (int kk = 0; kk < 2; kk++) {
            uint32_t afh[4][4], afl[4][4];
            {
                int row = wm * 64 + (lane & 15);
                int c   = kk * 2 + (lane >> 4);
                uint32_t off = (uint32_t)(row * 80 + c * 16);
#pragma unroll
                for (int t = 0; t < 4; t++) {
                    ldsm4(afh[t], stg + 0 * MG_ARR + off + t * (16 * 80));
                    ldsm4(afl[t], stg + 1 * MG_ARR + off + t * (16 * 80));
                }
            }
            uint32_t bf[8];
            {
                int n = wn * 32 + ((lane >> 4) * 8 + (lane & 7));
                int c = kk * 2 + ((lane >> 3) & 1);
                uint32_t off = (uint32_t)(n * 80 + c * 16);
                ldsm4(&bf[0], stg + 2 * MG_ARR + off);
                ldsm4(&bf[4], stg + 2 * MG_ARR + off + 16 * 80);
            }
#pragma unroll
            for (int t = 0; t < 4; t++)
#pragma unroll
                for (int n = 0; n < 4; n++) {
                    float* cc = acc[t * 4 + n];
                    mma16816h(cc, afh[t], &bf[n * 2]);
                    mma16816h(cc, afl[t], &bf[n * 2]);
                }
        }
        __syncthreads();
    }

#pragma unroll
    for (int t = 0; t < 4; t++)
#pragma unroll
        for (int n = 0; n < 4; n++) {
            int gr = by * 128 + wm * 64 + t * 16 + (lane >> 2);
            int gc = bx * 128 + wn * 32 + n * 8 + (lane & 3) * 2;
            float* cc = acc[t * 4 + n];
            *(float2*)&C[(size_t)gr * ldc + gc]       = make_float2(cc[0], cc[1]);
            *(float2*)&C[(size_t)(gr + 8) * ldc + gc] = make_float2(cc[2], cc[3]);
        }
}

// ============================================================================
// Conversions — single launch. z=0: Wqkv^T, z=1: Wkr^T, z=2: Wout^T,
// z=3: cat(h,x) + R single-fp16 rounding.
// ============================================================================
__global__ __launch_bounds__(256) void conv_all(
    const float* __restrict__ Wqkv, const float* __restrict__ Wkr,
    const float* __restrict__ Wout,
    const float* __restrict__ x, const float* __restrict__ h,
    const float* __restrict__ R)
{
    int z = blockIdx.z;
    if (z == 3) {
        int lb = blockIdx.x + blockIdx.y * 96;   // 0..3071
#pragma unroll
        for (int r = 0; r < 2; r++) {
            int blk = lb * 2 + r;
            if (blk >= 5120) break;
            if (blk < 4096) {
                int i = blk * 256 + threadIdx.x;
                int row = i >> 8, c4 = i & 255;
                int b = row >> 9, t = row & 511;
                const float4* src = (const float4*)((t < 256)
                    ? (h + ((size_t)b * 256 + t) * 1024)
                    : (x + ((size_t)b * 256 + (t - 256)) * 1024));
                float4 v = src[c4];
                ((uint2*)g_A)[i] = make_uint2(pack2s(v.x, v.y), pack2s(v.z, v.w));
            } else {
                int i = (blk - 4096) * 256 + threadIdx.x;
                float4 v = ((const float4*)R)[i];
                ((uint2*)g_AR)[i] = make_uint2(pack2s(v.x, v.y), pack2s(v.z, v.w));
            }
        }
        return;
    }

    const float* W; __half* Th; int N;
    if (z == 0)      { W = Wqkv; Th = g_B;  N = 3072; }
    else if (z == 1) { if (blockIdx.x >= 32) return; W = Wkr;  Th = g_BK; N = 1024; }
    else             { if (blockIdx.x >= 32) return; W = Wout; Th = g_BO; N = 1024; }

    __shared__ float ts[32][33];
    int n0 = blockIdx.x * 32, k0 = blockIdx.y * 32;
    int tx = threadIdx.x & 31, ty = threadIdx.x >> 5;
#pragma unroll
    for (int r = 0; r < 32; r += 8)
        ts[ty + r][tx] = W[(size_t)(k0 + ty + r) * N + n0 + tx];
    __syncthreads();
#pragma unroll
    for (int r = 0; r < 32; r += 8) {
        float v = ts[tx][ty + r];
        Th[(size_t)(n0 + ty + r) * 1024 + k0 + tx] = __float2half_rn(v);
    }
}

// cterm (blocks 0..8191) + dterm (8192..8705) + Ppad idx<64 fill (8706..9217)
__global__ __launch_bounds__(256) void cdterm(const float* __restrict__ u,
                                              const float* __restrict__ v)
{
    int blk = blockIdx.x;
    int lane = threadIdx.x & 31;
    if (blk < 8192) {
        int row = blk * 8 + (threadIdx.x >> 5);
        size_t o = (size_t)row * 64 + lane;
        float k0 = __half2float(g_kh[o]) + __half2float(g_kl[o]);
        float k1 = __half2float(g_kh[o + 32]) + __half2float(g_kl[o + 32]);
        float s = u[lane] * k0 + u[lane + 32] * k1;
#pragma unroll
        for (int of = 16; of; of >>= 1) s += __shfl_xor_sync(0xffffffffu, s, of);
        if (lane == 0) g_c[row] = s;
    } else if (blk < 8706) {
        int row = (blk - 8192) * 8 + (threadIdx.x >> 5);
        if (row >= 16 * 257) return;
        int hh = row / 257, t = row % 257;
        size_t base = (size_t)((t + 768) & 1023) * 1024 + hh * 64;
        float r0 = __half2float(g_RWh[base + lane]) + __half2float(g_RWl[base + lane]);
        float r1 = __half2float(g_RWh[base + lane + 32])
                 + __half2float(g_RWl[base + lane + 32]);
        float s = v[lane] * r0 + v[lane + 32] * r1;
#pragma unroll
        for (int of = 16; of; of >>= 1) s += __shfl_xor_sync(0xffffffffu, s, of);
        if (lane == 0) g_dt[row] = s;
    } else {
        int fid = blk - 8706;                // 0..511
        int bh = fid >> 2, it = fid & 3;
        int i0 = it * 64;
        float4 neg = make_float4(-1e30f, -1e30f, -1e30f, -1e30f);
#pragma unroll
        for (int l = 0; l < 4; l++) {
            int e = threadIdx.x + l * 256;
            int row = e >> 4, f4 = e & 15;
            *(float4*)&g_Pp[((size_t)bh * 256 + i0 + row) * 384 + f4 * 4] = neg;
        }
    }
}

// ============================================================================
// P GEMM v3 -> Ppad. One block per (it, bh); loops 5 t-tiles, q loaded once.
// fp16 3-MMA (q split x RW split, drop ql*RWl).
// ============================================================================
#define PG_LDB 144
__global__ __launch_bounds__(256) void p_gemm3()
{
    __shared__ char sm2[4 * 64 * PG_LDB];
    int it = blockIdx.x, bh = blockIdx.y;
    int hh = bh & 15;
    int i0 = it * 64;
    int tid = threadIdx.x, lane = tid & 31, wid = tid >> 5;

    uint32_t sb = smem_u32(sm2);
    uint32_t sQh = sb, sQl = sb + 9216, sBh = sb + 18432, sBl = sb + 27648;
    int wm = wid >> 1, wn = wid & 1;

    // q hi/lo once
#pragma unroll
    for (int l = 0; l < 2; l++) {
        int e = tid + l * 256;
        int row = e >> 3, c = e & 7;
        size_t qo = ((size_t)bh * 256 + i0 + row) * 64 + c * 8;
        *(uint4*)(sm2 + row * PG_LDB + c * 16) = *(const uint4*)&g_qh[qo];
        *(uint4*)(sm2 + 9216 + row * PG_LDB + c * 16) = *(const uint4*)&g_ql[qo];
    }

    for (int tt = 0; tt < 5; tt++) {
        if (tt > 0) __syncthreads();
#pragma unroll
        for (int l = 0; l < 2; l++) {
            int e = tid + l * 256;
            int row = e >> 3, c = e & 7;
            int t = tt * 64 + row;
            int rr = (t + 768) & 1023;
            size_t bo = (size_t)rr * 1024 + hh * 64 + c * 8;
            *(uint4*)(sm2 + 18432 + row * PG_LDB + c * 16) = *(const uint4*)&g_RWh[bo];
            *(uint4*)(sm2 + 27648 + row * PG_LDB + c * 16) = *(const uint4*)&g_RWl[bo];
        }
        __syncthreads();

        float acc[4][4];
#pragma unroll
        for (int n = 0; n < 4; n++)
#pragma unroll
            for (int j = 0; j < 4; j++) acc[n][j] = 0.f;

#pragma unroll
        for (int kk = 0; kk < 4; kk++) {
            uint32_t afh[4], afl[4];
            {
                int row = wm * 16 + (lane & 15);
                uint32_t off = (uint32_t)(row * PG_LDB + kk * 32 + (lane >> 4) * 16);
                ldsm4(afh, sQh + off);
                ldsm4(afl, sQl + off);
            }
            uint32_t bfh[8], bfl[8];
            {
                int n = wn * 32 + ((lane >> 4) * 8 + (lane & 7));
                uint32_t off = (uint32_t)(n * PG_LDB + kk * 32 + ((lane >> 3) & 1) * 16);
                ldsm4(&bfh[0], sBh + off);
                ldsm4(&bfh[4], sBh + off + 16 * PG_LDB);
                ldsm4(&bfl[0], sBl + off);
                ldsm4(&bfl[4], sBl + off + 16 * PG_LDB);
            }
#pragma unroll
            for (int n = 0; n < 4; n++) {
                mma16816h(acc[n], afh, &bfh[n * 2]);
                mma16816h(acc[n], afh, &bfl[n * 2]);
                mma16816h(acc[n], afl, &bfh[n * 2]);
            }
        }

#pragma unroll
        for (int n = 0; n < 4; n++) {
            int tl = wn * 32 + n * 8 + (lane & 3) * 2;
#pragma unroll
            for (int half = 0; half < 2; half++) {
                int ii = i0 + wm * 16 + (lane >> 2) + half * 8;
#pragma unroll
                for (int e = 0; e < 2; e++) {
                    int t = tt * 64 + tl + e;
                    float a = acc[n][half * 2 + e];
                    float val = -1e30f;
                    if (t < 257)
                        val = a + 0.125f * (g_c[(size_t)bh * 512 + ii + t]
                                            + g_dt[hh * 257 + t]);
                    g_Pp[((size_t)bh * 256 + ii) * 384 + t + 64] = val;
                }
            }
        }
    }
}

// ============================================================================
// Fused attention (register softmax), fp16 3-MMA (unchanged)
// ============================================================================
#define AT_LDB 144
__global__ __launch_bounds__(256) void attn_mma2()
{
    __shared__ char sma[36864 + 1024];
    uint32_t sb = smem_u32(sma);
    uint32_t sQh = sb, sQl = sb + 9216;
    uint32_t sKh = sb + 18432, sKl = sb + 27648;
    float* sRed = (float*)(sma + 36864);
    float* sO   = (float*)sma;

    int it = blockIdx.x, bh = blockIdx.y;
    int hh = bh & 15, bb = bh >> 4;
    int i0 = it * 64;
    int tid = threadIdx.x, lane = tid & 31, wid = tid >> 5;
    int wm = wid >> 1, wn = wid & 1;

#pragma unroll
    for (int l = 0; l < 2; l++) {
        int e = tid + l * 256, row = e >> 3, c = e & 7;
        size_t qo = ((size_t)bh * 256 + i0 + row) * 64 + c * 8;
        *(uint4*)(sma + row * AT_LDB + c * 16) = *(const uint4*)&g_qh[qo];
        *(uint4*)(sma + 9216 + row * AT_LDB + c * 16) = *(const uint4*)&g_ql[qo];
    }

    float sc[5][4][4];
#pragma unroll
    for (int jt = 0; jt < 5; jt++)
#pragma unroll
        for (int n = 0; n < 4; n++)
#pragma unroll
            for (int j = 0; j < 4; j++) sc[jt][n][j] = 0.f;

#pragma unroll
    for (int jt = 0; jt < 5; jt++) {
#pragma unroll
        for (int l = 0; l < 2; l++) {
            int e = tid + l * 256, row = e >> 3, c = e & 7;
            size_t ko = ((size_t)bh * 512 + i0 + jt * 64 + row) * 64 + c * 8;
            *(uint4*)(sma + 18432 + row * AT_LDB + c * 16) = *(const uint4*)&g_kh[ko];
            *(uint4*)(sma + 27648 + row * AT_LDB + c * 16) = *(const uint4*)&g_kl[ko];
        }
        __syncthreads();
#pragma unroll
        for (int kk = 0; kk < 4; kk++) {
            uint32_t afh[4], afl[4];
            {
                int row = wm * 16 + (lane & 15);
                uint32_t off = (uint32_t)(row * AT_LDB + kk * 32 + (lane >> 4) * 16);
                ldsm4(afh, sQh + off);
                ldsm4(afl, sQl + off);
            }
            uint32_t bfh[8], bfl[8];
            {
                int n = wn * 32 + ((lane >> 4) * 8 + (lane & 7));
                uint32_t off = (uint32_t)(n * AT_LDB + kk * 32 + ((lane >> 3) & 1) * 16);
                ldsm4(&bfh[0], sKh + off);
                ldsm4(&bfh[4], sKh + off + 16 * AT_LDB);
                ldsm4(&bfl[0], sKl + off);
                ldsm4(&bfl[4], sKl + off + 16 * AT_LDB);
            }
#pragma unroll
            for (int n = 0; n < 4; n++) {
                mma16816h(sc[jt][n], afh, &bfh[n * 2]);
                mma16816h(sc[jt][n], afh, &bfl[n * 2]);
                mma16816h(sc[jt][n], afl, &bfh[n * 2]);
            }
        }
        __syncthreads();
    }

    int r1 = wm * 16 + (lane >> 2), r2 = r1 + 8;
    const float* P1 = &g_Pp[((size_t)bh * 256 + i0 + r1) * 384 + 64 - r1];
    const float* P2 = &g_Pp[((size_t)bh * 256 + i0 + r2) * 384 + 64 - r2];
    float m1 = -1e30f, m2 = -1e30f;
#pragma unroll
    for (int jt = 0; jt < 5; jt++)
#pragma unroll
        for (int n = 0; n < 4; n++) {
            int col = jt * 64 + wn * 32 + n * 8 + (lane & 3) * 2;
            sc[jt][n][0] += P1[col];     sc[jt][n][1] += P1[col + 1];
            sc[jt][n][2] += P2[col];     sc[jt][n][3] += P2[col + 1];
            m1 = fmaxf(m1, fmaxf(sc[jt][n][0], sc[jt][n][1]));
            m2 = fmaxf(m2, fmaxf(sc[jt][n][2], sc[jt][n][3]));
        }
    m1 = fmaxf(m1, __shfl_xor_sync(0xffffffffu, m1, 1));
    m1 = fmaxf(m1, __shfl_xor_sync(0xffffffffu, m1, 2));
    m2 = fmaxf(m2, __shfl_xor_sync(0xffffffffu, m2, 1));
    m2 = fmaxf(m2, __shfl_xor_sync(0xffffffffu, m2, 2));
    if ((lane & 3) == 0) { sRed[r1 * 4 + wn] = m1; sRed[r2 * 4 + wn] = m2; }
    __syncthreads();
    m1 = fmaxf(sRed[r1 * 4 + 0], sRed[r1 * 4 + 1]);
    m2 = fmaxf(sRed[r2 * 4 + 0], sRed[r2 * 4 + 1]);

    float s1 = 0.f, s2 = 0.f;
#pragma unroll
    for (int jt = 0; jt < 5; jt++)
#pragma unroll
        for (int n = 0; n < 4; n++) {
            float e0 = __expf(sc[jt][n][0] - m1);
            float e1 = __expf(sc[jt][n][1] - m1);
            float e2 = __expf(sc[jt][n][2] - m2);
            float e3 = __expf(sc[jt][n][3] - m2);
            sc[jt][n][0] = e0; sc[jt][n][1] = e1;
            sc[jt][n][2] = e2; sc[jt][n][3] = e3;
            s1 += e0 + e1; s2 += e2 + e3;
        }
    s1 += __shfl_xor_sync(0xffffffffu, s1, 1);
    s1 += __shfl_xor_sync(0xffffffffu, s1, 2);
    s2 += __shfl_xor_sync(0xffffffffu, s2, 1);
    s2 += __shfl_xor_sync(0xffffffffu, s2, 2);
    if ((lane & 3) == 0) { sRed[r1 * 4 + 2 + wn] = s1; sRed[r2 * 4 + 2 + wn] = s2; }
    __syncthreads();
    float inv1 = 1.f / (sRed[r1 * 4 + 2] + sRed[r1 * 4 + 3]);
    float inv2 = 1.f / (sRed[r2 * 4 + 2] + sRed[r2 * 4 + 3]);

    uint32_t ph[5][2][4], pl[5][2][4];
#pragma unroll
    for (int jt = 0; jt < 5; jt++)
#pragma unroll
        for (int t = 0; t < 2; t++) {
            pack2h(sc[jt][2*t][0] * inv1, sc[jt][2*t][1] * inv1,
                   ph[jt][t][0], pl[jt][t][0]);
            pack2h(sc[jt][2*t][2] * inv2, sc[jt][2*t][3] * inv2,
                   ph[jt][t][1], pl[jt][t][1]);
            pack2h(sc[jt][2*t+1][0] * inv1, sc[jt][2*t+1][1] * inv1,
                   ph[jt][t][2], pl[jt][t][2]);
            pack2h(sc[jt][2*t+1][2] * inv2, sc[jt][2*t+1][3] * inv2,
                   ph[jt][t][3], pl[jt][t][3]);
        }

    float oacc[8][4];
#pragma unroll
    for (int n = 0; n < 8; n++)
#pragma unroll
        for (int j = 0; j < 4; j++) oacc[n][j] = 0.f;

#pragma unroll
    for (int jt = 0; jt < 5; jt++) {
#pragma unroll
        for (int l = 0; l < 2; l++) {
            int e = tid + l * 256, row = e >> 3, c = e & 7;
            size_t vo = ((size_t)bh * 512 + i0 + jt * 64 + row) * 64 + c * 8;
            *(uint4*)(sma + 18432 + row * AT_LDB + c * 16) = *(const uint4*)&g_vh[vo];
            *(uint4*)(sma + 27648 + row * AT_LDB + c * 16) = *(const uint4*)&g_vl[vo];
        }
        __syncthreads();
#pragma unroll
        for (int t = 0; t < 2; t++) {
            uint32_t bfh[16], bfl[16];
            int g = lane >> 3;
            int kr = (g & 1) * 8 + (lane & 7);
            int nc = (g >> 1) * 8;
            uint32_t base = (uint32_t)((wn * 32 + t * 16 + kr) * AT_LDB + nc * 2);
#pragma unroll
            for (int dd = 0; dd < 4; dd++) {
                ldsm4t(&bfh[dd * 4], sKh + base + dd * 32);
                ldsm4t(&bfl[dd * 4], sKl + base + dd * 32);
            }
#pragma unroll
            for (int n = 0; n < 8; n++) {
                const uint32_t* bh_ = &bfh[(n >> 1) * 4 + (n & 1) * 2];
                const uint32_t* bl_ = &bfl[(n >> 1) * 4 + (n & 1) * 2];
                mma16816h(oacc[n], ph[jt][t], bh_);
                mma16816h(oacc[n], ph[jt][t], bl_);
                mma16816h(oacc[n], pl[jt][t], bh_);
            }
        }
        __syncthreads();
    }

    if (wn == 0) {
#pragma unroll
        for (int n = 0; n < 8; n++) {
            int c0 = n * 8 + (lane & 3) * 2;
            sO[r1 * 66 + c0]     = oacc[n][0];
            sO[r1 * 66 + c0 + 1] = oacc[n][1];
            sO[r2 * 66 + c0]     = oacc[n][2];
            sO[r2 * 66 + c0 + 1] = oacc[n][3];
        }
    }
    __syncthreads();
    if (wn == 1) {
#pragma unroll
        for (int n = 0; n < 8; n++) {
            int c0 = n * 8 + (lane & 3) * 2;
            float a0 = oacc[n][0] + sO[r1 * 66 + c0];
            float a1 = oacc[n][1] + sO[r1 * 66 + c0 + 1];
            float a2 = oacc[n][2] + sO[r2 * 66 + c0];
            float a3 = oacc[n][3] + sO[r2 * 66 + c0 + 1];
            uint32_t H, L;
            pack2h(a0, a1, H, L);
            size_t o1 = ((size_t)bb * 256 + i0 + r1) * 1024 + hh * 64 + c0;
            *(uint32_t*)&g_Oh[o1] = H; *(uint32_t*)&g_Ol[o1] = L;
            pack2h(a2, a3, H, L);
            size_t o2 = ((size_t)bb * 256 + i0 + r2) * 1024 + hh * 64 + c0;
            *(uint32_t*)&g_Oh[o2] = H; *(uint32_t*)&g_Ol[o2] = L;
        }
    }
}

// ============================================================================
// kernel_launch
// ============================================================================
extern "C" void kernel_launch(void* const* d_in, const int* in_sizes, int n_in,
                              void* d_out, int out_size)
{
    const float* x    = (const float*)d_in[0];
    const float* h    = (const float*)d_in[1];
    const float* Wqkv = (const float*)d_in[2];
    const float* Wkr  = (const float*)d_in[3];
    const float* R    = (const float*)d_in[4];
    const float* u    = (const float*)d_in[5];
    const float* v    = (const float*)d_in[6];
    const float* Wout = (const float*)d_in[7];
    float* out = (float*)d_out;

    __half *pA, *pB, *pBO, *pOh, *pOl;
    cudaGetSymbolAddress((void**)&pA,  g_A);
    cudaGetSymbolAddress((void**)&pB,  g_B);
    cudaGetSymbolAddress((void**)&pBO, g_BO);
    cudaGetSymbolAddress((void**)&pOh, g_Oh);
    cudaGetSymbolAddress((void**)&pOl, g_Ol);

    cudaFuncSetAttribute(mma_gemm1, cudaFuncAttributeMaxDynamicSharedMemorySize,
                         M1_SMEM);
    cudaFuncSetAttribute(mma_gemm_out, cudaFuncAttributeMaxDynamicSharedMemorySize,
                         MG_SMEM);

    // all conversions in one launch
    conv_all<<<dim3(96, 32, 4), 256>>>(Wqkv, Wkr, Wout, x, h, R);

    // qkv GEMM (z=0, mode 1) + RW GEMM (z=1, mode 2), single-A
    mma_gemm1<<<dim3(24, 32, 2), 256, M1_SMEM>>>(pA, pB, 1);

    // bias terms + Ppad fill, then P (folds c + dt)
    cdterm<<<9218, 256>>>(u, v);
    p_gemm3<<<dim3(4, 128), 256>>>();

    // fused attention
    attn_mma2<<<dim3(4, 128), 256>>>();

    // out = O @ Wout (split-A, 2 MMA)
    mma_gemm_out<<<dim3(8, 16), 256, MG_SMEM>>>(pOh, pOl, pBO, out, 1024);
}